// round 7
// baseline (speedup 1.0000x reference)
#include <cuda_runtime.h>
#include <cstdint>

#define NSEQ 2048
#define SCALEQ 0.18033688011112042f   // (1/sqrt(64)) * log2(e)

static const size_t ATT_OFF = 2097152;   // 16*2048*64

// ---- main kernel smem (floats) ----
#define QP    0        // Q (prologue) / P staging (loop): 128 x 68
#define KS0   8704     // 64 x 68
#define KS1   13056
#define VS0   17408    // 64 x 72
#define VS1   22016
#define MMSK  26624    // 64 u32
#define SMEMF_MAIN 26688   // 106,752 B

// ---- stats kernel smem (floats) ----
#define SQS   0        // 128 x 68
#define SKS0  8704
#define SKS1  13056
#define SMSK  17408    // 64 u32
#define SLP   17472    // 4 x 128
#define SMEMF_STATS 17984  // 71,936 B

__device__ float g_rri[16 * 2048];   // per-row 1/l scratch (static, no alloc)

__device__ __forceinline__ uint32_t smem_u32(const void* p) {
    uint32_t a;
    asm("{ .reg .u64 t; cvta.to.shared.u64 t, %1; cvt.u32.u64 %0, t; }" : "=r"(a) : "l"(p));
    return a;
}
__device__ __forceinline__ float ex2f_(float x) {
    float y; asm("ex2.approx.ftz.f32 %0, %1;" : "=f"(y) : "f"(x)); return y;
}
__device__ __forceinline__ unsigned cvt_tf32(float x) {
    unsigned y; asm("cvt.rna.tf32.f32 %0, %1;" : "=r"(y) : "f"(x)); return y;
}
__device__ __forceinline__ void mma_tf32(float c[4],
                                         unsigned a0, unsigned a1, unsigned a2, unsigned a3,
                                         unsigned b0, unsigned b1) {
    asm volatile(
        "mma.sync.aligned.m16n8k8.row.col.f32.tf32.tf32.f32 "
        "{%0,%1,%2,%3}, {%4,%5,%6,%7}, {%8,%9}, {%0,%1,%2,%3};"
        : "+f"(c[0]), "+f"(c[1]), "+f"(c[2]), "+f"(c[3])
        : "r"(a0), "r"(a1), "r"(a2), "r"(a3), "r"(b0), "r"(b1));
}

__device__ __forceinline__ void cp16(uint32_t dst, const void* src) {
    asm volatile("cp.async.cg.shared.global [%0], [%1], 16;" :: "r"(dst), "l"(src) : "memory");
}
#define CP_COMMIT() asm volatile("cp.async.commit_group;" ::: "memory")
#define CP_WAIT0()  asm volatile("cp.async.wait_group 0;" ::: "memory")

// issue one 64x64 fp32 tile: global -> smem (row stride strideB bytes), 2 chunks/thread
// 64 rows x 256B; 1024 chunks of 16B: row = idx>>4, col16 = (idx&15)*16.
__device__ __forceinline__ void issue_tile(uint32_t buf, const float* src, int tid, int strideB) {
#pragma unroll
    for (int it = 0; it < 2; ++it) {
        int idx = tid + it * 512;
        int row = idx >> 4, c16 = (idx & 15) << 4;
        cp16(buf + row * strideB + c16, (const char*)src + row * 256 + c16);
    }
}

// shared S-tile compute: identical instruction sequence in both kernels (bitwise-equal scores)
__device__ __forceinline__ void compute_S(const unsigned aq[8][2][4], const float* __restrict__ Ks,
                                          int wn, int g, int tig, float c[2][2][4]) {
#pragma unroll
    for (int ms = 0; ms < 2; ++ms)
#pragma unroll
        for (int nt = 0; nt < 2; ++nt)
#pragma unroll
            for (int e = 0; e < 4; ++e) c[ms][nt][e] = 0.f;
#pragma unroll
    for (int ks = 0; ks < 8; ++ks) {
#pragma unroll
        for (int nt = 0; nt < 2; ++nt) {
            const float* kr = Ks + (wn * 16 + nt * 8 + g) * 68 + ks * 8;
            unsigned b0 = cvt_tf32(kr[tig]);
            unsigned b1 = cvt_tf32(kr[tig + 4]);
            mma_tf32(c[0][nt], aq[ks][0][0], aq[ks][0][1], aq[ks][0][2], aq[ks][0][3], b0, b1);
            mma_tf32(c[1][nt], aq[ks][1][0], aq[ks][1][1], aq[ks][1][2], aq[ks][1][3], b0, b1);
        }
    }
}

// load Q (scaled, tf32) + mask bitwords into smem
__device__ __forceinline__ void prologue_qm(float* sm, int qoff, int moff,
                                            const float* qg, const int* mg, int tid) {
#pragma unroll
    for (int it = 0; it < 4; ++it) {
        int idx = tid + it * 512;
        int r = idx >> 4, c4 = (idx & 15) << 2;
        float4 t = *(const float4*)(qg + r * 64 + c4);
        uint4 u;
        u.x = cvt_tf32(t.x * SCALEQ); u.y = cvt_tf32(t.y * SCALEQ);
        u.z = cvt_tf32(t.z * SCALEQ); u.w = cvt_tf32(t.w * SCALEQ);
        *(uint4*)(sm + qoff + r * 68 + c4) = u;
    }
    if (tid < 64) {
        unsigned bits = 0;
#pragma unroll 8
        for (int r = 0; r < 32; ++r) bits |= (mg[tid * 32 + r] != 0 ? 1u : 0u) << r;
        ((unsigned*)(sm + moff))[tid] = bits;
    }
}

__device__ __forceinline__ void load_aq(unsigned aq[8][2][4], const float* sm, int qoff,
                                        int wm, int g, int tig) {
#pragma unroll
    for (int ks = 0; ks < 8; ++ks)
#pragma unroll
        for (int ms = 0; ms < 2; ++ms) {
            const float* qr = sm + qoff + (wm * 32 + ms * 16 + g) * 68 + ks * 8;
            aq[ks][ms][0] = __float_as_uint(qr[tig]);
            aq[ks][ms][1] = __float_as_uint(qr[8 * 68 + tig]);
            aq[ks][ms][2] = __float_as_uint(qr[tig + 4]);
            aq[ks][ms][3] = __float_as_uint(qr[8 * 68 + tig + 4]);
        }
}

// =============== Kernel 1: row-sum stats -> g_rri ===============
__global__ void __launch_bounds__(512, 1)
lg_stats(const float* __restrict__ q, const float* __restrict__ k,
         const int* __restrict__ mask) {
    extern __shared__ float sm[];
    const uint32_t sbu = smem_u32(sm);
    const int tid = threadIdx.x;
    const int w = tid >> 5, lane = tid & 31;
    const int wm = w & 3, wn = w >> 2;
    const int g = lane >> 2, tig = lane & 3;

    const int bh = blockIdx.y, b = bh >> 2;
    const int i0 = blockIdx.x * 128;
    const float* qg = q + ((size_t)bh * NSEQ + i0) * 64;
    const float* kg = k + (size_t)bh * NSEQ * 64;
    const int* mg = mask + (size_t)b * NSEQ;
    const unsigned* mw = (const unsigned*)(sm + SMSK);

    prologue_qm(sm, SQS, SMSK, qg, mg, tid);
    issue_tile(sbu + SKS0 * 4, kg, tid, 272);
    CP_COMMIT();
    __syncthreads();

    unsigned aq[8][2][4];
    load_aq(aq, sm, SQS, wm, g, tig);

    float l[4] = {0.f, 0.f, 0.f, 0.f};

    for (int j = 0; j < 32; ++j) {
        CP_WAIT0();
        __syncthreads();
        if (j < 31) {
            issue_tile(sbu + (((j + 1) & 1) ? SKS1 : SKS0) * 4, kg + (size_t)(j + 1) * 64 * 64, tid, 272);
            CP_COMMIT();
        }
        float c[2][2][4];
        compute_S(aq, sm + ((j & 1) ? SKS1 : SKS0), wn, g, tig, c);

        unsigned wbits = mw[2 * j + (wn >> 1)];
#pragma unroll
        for (int ms = 0; ms < 2; ++ms)
#pragma unroll
            for (int nt = 0; nt < 2; ++nt) {
                int base = (wn & 1) * 16 + nt * 8 + 2 * tig;
                float e0 = ((wbits >> base) & 1u) ? ex2f_(c[ms][nt][0]) : 0.f;
                float e1 = ((wbits >> (base + 1)) & 1u) ? ex2f_(c[ms][nt][1]) : 0.f;
                float e2 = ((wbits >> base) & 1u) ? ex2f_(c[ms][nt][2]) : 0.f;
                float e3 = ((wbits >> (base + 1)) & 1u) ? ex2f_(c[ms][nt][3]) : 0.f;
                l[ms * 2] += e0 + e1;
                l[ms * 2 + 1] += e2 + e3;
            }
    }

    // reduce: 4 tig lanes per row, then 4 wn groups
#pragma unroll
    for (int s = 0; s < 4; ++s) {
        l[s] += __shfl_xor_sync(0xffffffffu, l[s], 1);
        l[s] += __shfl_xor_sync(0xffffffffu, l[s], 2);
    }
    if (tig == 0) {
#pragma unroll
        for (int s = 0; s < 4; ++s) {
            int row = wm * 32 + (s >> 1) * 16 + g + (s & 1) * 8;
            sm[SLP + wn * 128 + row] = l[s];
        }
    }
    __syncthreads();
    if (tid < 128) {
        float lt = sm[SLP + tid] + sm[SLP + 128 + tid] + sm[SLP + 256 + tid] + sm[SLP + 384 + tid];
        g_rri[(size_t)bh * NSEQ + i0 + tid] = 1.0f / lt;
    }
}

// =============== Kernel 2: single pass — P, attention, O ===============
__global__ void __launch_bounds__(512, 1)
lg_main(const float* __restrict__ q, const float* __restrict__ k,
        const float* __restrict__ v, const int* __restrict__ mask,
        float* __restrict__ out) {
    extern __shared__ float sm[];
    const uint32_t sbu = smem_u32(sm);
    const int tid = threadIdx.x;
    const int w = tid >> 5, lane = tid & 31;
    const int wm = w & 3, wn = w >> 2;
    const int g = lane >> 2, tig = lane & 3;

    const int bh = blockIdx.y, b = bh >> 2;
    const int i0 = blockIdx.x * 128;
    const float* qg = q + ((size_t)bh * NSEQ + i0) * 64;
    const float* kg = k + (size_t)bh * NSEQ * 64;
    const float* vg = v + (size_t)bh * NSEQ * 64;
    const int* mg = mask + (size_t)b * NSEQ;
    float* attg = out + ATT_OFF + ((size_t)bh * NSEQ + i0) * NSEQ;
    const unsigned* mw = (const unsigned*)(sm + MMSK);

    prologue_qm(sm, QP, MMSK, qg, mg, tid);
    issue_tile(sbu + KS0 * 4, kg, tid, 272);
    issue_tile(sbu + VS0 * 4, vg, tid, 288);
    CP_COMMIT();
    __syncthreads();

    unsigned aq[8][2][4];
    load_aq(aq, sm, QP, wm, g, tig);

    float rri[4];
#pragma unroll
    for (int s = 0; s < 4; ++s) {
        int row = wm * 32 + (s >> 1) * 16 + g + (s & 1) * 8;
        rri[s] = g_rri[(size_t)bh * NSEQ + i0 + row];
    }

    float o[2][2][4];
#pragma unroll
    for (int ms = 0; ms < 2; ++ms)
#pragma unroll
        for (int nt = 0; nt < 2; ++nt)
#pragma unroll
            for (int e = 0; e < 4; ++e) o[ms][nt][e] = 0.f;

    float* Pm = sm + QP + wm * (32 * 68);   // P staging overlays dead Q region

    for (int j = 0; j < 32; ++j) {
        CP_WAIT0();
        __syncthreads();   // K/V(j) ready; all threads done with K/V(j-1) and P(j-1)
        if (j < 31) {
            issue_tile(sbu + (((j + 1) & 1) ? KS1 : KS0) * 4, kg + (size_t)(j + 1) * 64 * 64, tid, 272);
            issue_tile(sbu + (((j + 1) & 1) ? VS1 : VS0) * 4, vg + (size_t)(j + 1) * 64 * 64, tid, 288);
            CP_COMMIT();
        }

        float c[2][2][4];
        compute_S(aq, sm + ((j & 1) ? KS1 : KS0), wn, g, tig, c);

        unsigned wbits = mw[2 * j + (wn >> 1)];
#pragma unroll
        for (int ms = 0; ms < 2; ++ms)
#pragma unroll
            for (int nt = 0; nt < 2; ++nt) {
                int base = (wn & 1) * 16 + nt * 8 + 2 * tig;
                float p0 = ((wbits >> base) & 1u) ? ex2f_(c[ms][nt][0]) * rri[2 * ms] : 0.f;
                float p1 = ((wbits >> (base + 1)) & 1u) ? ex2f_(c[ms][nt][1]) * rri[2 * ms] : 0.f;
                float p2 = ((wbits >> base) & 1u) ? ex2f_(c[ms][nt][2]) * rri[2 * ms + 1] : 0.f;
                float p3 = ((wbits >> (base + 1)) & 1u) ? ex2f_(c[ms][nt][3]) * rri[2 * ms + 1] : 0.f;

                int row = wm * 32 + ms * 16 + g;
                int col = j * 64 + wn * 16 + nt * 8 + 2 * tig;
                *(float2*)(attg + (size_t)row * NSEQ + col) = make_float2(p0, p1);
                *(float2*)(attg + (size_t)(row + 8) * NSEQ + col) = make_float2(p2, p3);

                int lr = ms * 16 + g, lc = wn * 16 + nt * 8 + 2 * tig;
                *(uint2*)(Pm + lr * 68 + lc) = make_uint2(cvt_tf32(p0), cvt_tf32(p1));
                *(uint2*)(Pm + (lr + 8) * 68 + lc) = make_uint2(cvt_tf32(p2), cvt_tf32(p3));
            }
        __syncthreads();   // P(j) visible to all warps of this wm group

        // O += P * V over all 64 keys; this warp owns d-columns wn*16..wn*16+15
        const float* Vs = sm + ((j & 1) ? VS1 : VS0);
#pragma unroll
        for (int kb = 0; kb < 8; ++kb) {
            unsigned a[2][4];
#pragma unroll
            for (int ms = 0; ms < 2; ++ms) {
                const float* pr = Pm + (ms * 16 + g) * 68 + kb * 8;
                a[ms][0] = __float_as_uint(pr[tig]);
                a[ms][1] = __float_as_uint(pr[8 * 68 + tig]);
                a[ms][2] = __float_as_uint(pr[tig + 4]);
                a[ms][3] = __float_as_uint(pr[8 * 68 + tig + 4]);
            }
#pragma unroll
            for (int nt = 0; nt < 2; ++nt) {
                unsigned b0 = cvt_tf32(Vs[(kb * 8 + tig) * 72 + wn * 16 + nt * 8 + g]);
                unsigned b1 = cvt_tf32(Vs[(kb * 8 + tig + 4) * 72 + wn * 16 + nt * 8 + g]);
                mma_tf32(o[0][nt], a[0][0], a[0][1], a[0][2], a[0][3], b0, b1);
                mma_tf32(o[1][nt], a[1][0], a[1][1], a[1][2], a[1][3], b0, b1);
            }
        }
        // next iteration's top __syncthreads protects P/K/V reuse
    }

    // O store (already normalized)
#pragma unroll
    for (int ms = 0; ms < 2; ++ms)
#pragma unroll
        for (int nt = 0; nt < 2; ++nt) {
            int row = wm * 32 + ms * 16 + g;
            int col = wn * 16 + nt * 8 + 2 * tig;
            float* og0 = out + ((size_t)bh * NSEQ + i0 + row) * 64 + col;
            float* og1 = out + ((size_t)bh * NSEQ + i0 + row + 8) * 64 + col;
            *(float2*)og0 = make_float2(o[ms][nt][0], o[ms][nt][1]);
            *(float2*)og1 = make_float2(o[ms][nt][2], o[ms][nt][3]);
        }
}

extern "C" void kernel_launch(void* const* d_in, const int* in_sizes, int n_in,
                              void* d_out, int out_size) {
    const float* q = (const float*)d_in[0];
    const float* k = (const float*)d_in[1];
    const float* v = (const float*)d_in[2];
    const int* mask = (const int*)d_in[3];
    float* out = (float*)d_out;

    const int smemS = SMEMF_STATS * (int)sizeof(float);   // 71,936 B
    const int smemM = SMEMF_MAIN * (int)sizeof(float);    // 106,752 B
    cudaFuncSetAttribute(lg_stats, cudaFuncAttributeMaxDynamicSharedMemorySize, smemS);
    cudaFuncSetAttribute(lg_main, cudaFuncAttributeMaxDynamicSharedMemorySize, smemM);

    dim3 grid(NSEQ / 128, 16);
    lg_stats<<<grid, 512, smemS>>>(q, k, mask);
    lg_main<<<grid, 512, smemM>>>(q, k, v, mask, out);
}